// round 14
// baseline (speedup 1.0000x reference)
#include <cuda_runtime.h>
#include <cstdint>
#include <math.h>

// Problem dims (fixed by the reference)
#define BB 8
#define SS 2048
#define EE 512
#define HH 8
#define DD 64
#define BS (BB*SS)          // 16384 rows

// Scratch: q,k,v hold PRE-CONVERTED tf32 bit patterns; att holds fp32.
__device__ uint32_t g_q[BB*HH*SS*DD];
__device__ uint32_t g_k[BB*HH*SS*DD];
__device__ uint32_t g_v[BB*HH*SS*DD];
__device__ float    g_att[BB*HH*SS*DD];

static __device__ __forceinline__ uint32_t cvt_tf32(float f) {
    uint32_t r; asm("cvt.rna.tf32.f32 %0, %1;" : "=r"(r) : "f"(f)); return r;
}
static __device__ __forceinline__ uint4 cvt4(float4 g) {
    uint4 t;
    t.x = cvt_tf32(g.x); t.y = cvt_tf32(g.y);
    t.z = cvt_tf32(g.z); t.w = cvt_tf32(g.w);
    return t;
}

// m16n8k8 tf32 mma.sync (baseline PTX — no sm_103a-only features)
#define MMA_TF32(c, a, b) \
    asm volatile("mma.sync.aligned.m16n8k8.row.col.f32.tf32.tf32.f32 " \
        "{%0,%1,%2,%3}, {%4,%5,%6,%7}, {%8,%9}, {%0,%1,%2,%3};" \
        : "+f"((c)[0]), "+f"((c)[1]), "+f"((c)[2]), "+f"((c)[3]) \
        : "r"((a)[0]), "r"((a)[1]), "r"((a)[2]), "r"((a)[3]), \
          "r"((b)[0]), "r"((b)[1]))

// ===========================================================================
// Kernel 1: fused QKV projection, M-tile 64, 2 CTAs/SM.
// Per CTA: one head h, 64 M-rows, N=192 (q|k|v), K=512 in BK=32 chunks.
// 8 warps as 2(M)x4(N): warp tile 32x48 = 2 m16 x 6 n8.
// R8 loop structure: STS -> sync -> prefetch LDG -> MMA -> sync.
// ===========================================================================
__global__ __launch_bounds__(256, 2)
void qkv_mma_kernel(const float* __restrict__ x,
                    const float* __restrict__ Wq,
                    const float* __restrict__ Wk,
                    const float* __restrict__ Wv)
{
    __shared__ uint32_t Xs[64 * 36];      //  9216 B
    __shared__ uint32_t Ws[32 * 200];     // 25600 B  (34.8 KB total)

    const int tid  = threadIdx.x;
    const int wid  = tid >> 5;
    const int lane = tid & 31;
    const int h  = blockIdx.x;
    const int m0 = blockIdx.y * 64;
    const int wm = wid >> 2;              // 0..1
    const int wn = wid & 3;               // 0..3
    const int g   = lane >> 2;            // 0..7
    const int tig = lane & 3;             // 0..3

    // X: rows xrow, xrow+32; 2 float4/thread
    const int xrow = tid >> 3;            // 0..31
    const int xc4  = tid & 7;
    const float* xptr[2];
    #pragma unroll
    for (int i = 0; i < 2; i++)
        xptr[i] = x + (size_t)(m0 + xrow + 32 * i) * EE + xc4 * 4;

    // W: 6 float4/thread (3 tensors x 32x64 tile)
    const int we  = tid >> 4;
    const int wd4 = tid & 15;
    const float* Wsel[3] = { Wq + (size_t)h * EE * DD,
                             Wk + (size_t)h * EE * DD,
                             Wv + (size_t)h * EE * DD };
    const float* wptr[6];
    uint32_t wsoff[6];
    #pragma unroll
    for (int i = 0; i < 6; i++) {
        const int t = i >> 1;
        const int e = we + (i & 1) * 16;
        wptr[i] = Wsel[t] + (size_t)e * DD + wd4 * 4;
        wsoff[i] = e * 200 + t * 64 + wd4 * 4;
    }
    const uint32_t xsoff = xrow * 36 + xc4 * 4;

    float acc[2][6][4];
    #pragma unroll
    for (int mi = 0; mi < 2; mi++)
        #pragma unroll
        for (int ni = 0; ni < 6; ni++)
            #pragma unroll
            for (int j = 0; j < 4; j++) acc[mi][ni][j] = 0.f;

    // prologue: prefetch chunk 0
    float4 xr[2], wr[6];
    #pragma unroll
    for (int i = 0; i < 2; i++) xr[i] = *(const float4*)xptr[i];
    #pragma unroll
    for (int i = 0; i < 6; i++) wr[i] = *(const float4*)wptr[i];

    for (int c = 0; c < 16; c++) {
        // stage current chunk to smem
        #pragma unroll
        for (int i = 0; i < 2; i++)
            *(uint4*)&Xs[xsoff + i * (32 * 36)] = cvt4(xr[i]);
        #pragma unroll
        for (int i = 0; i < 6; i++)
            *(uint4*)&Ws[wsoff[i]] = cvt4(wr[i]);
        __syncthreads();

        // prefetch next chunk (latency hidden behind the MMA block)
        if (c < 15) {
            #pragma unroll
            for (int i = 0; i < 2; i++)
                xr[i] = *(const float4*)(xptr[i] + (c + 1) * 32);
            #pragma unroll
            for (int i = 0; i < 6; i++)
                wr[i] = *(const float4*)(wptr[i] + (size_t)(c + 1) * 32 * DD);
        }

        #pragma unroll
        for (int s = 0; s < 4; s++) {
            const int kk = s * 8;
            uint32_t a[2][4];
            #pragma unroll
            for (int mi = 0; mi < 2; mi++) {
                const int mb = wm * 32 + mi * 16;
                a[mi][0] = Xs[(mb + g    ) * 36 + kk + tig];
                a[mi][1] = Xs[(mb + g + 8) * 36 + kk + tig];
                a[mi][2] = Xs[(mb + g    ) * 36 + kk + tig + 4];
                a[mi][3] = Xs[(mb + g + 8) * 36 + kk + tig + 4];
            }
            uint32_t b[6][2];
            #pragma unroll
            for (int ni = 0; ni < 6; ni++) {
                const int nb = wn * 48 + ni * 8;
                b[ni][0] = Ws[(kk + tig    ) * 200 + nb + g];
                b[ni][1] = Ws[(kk + tig + 4) * 200 + nb + g];
            }
            #pragma unroll
            for (int mi = 0; mi < 2; mi++)
                #pragma unroll
                for (int ni = 0; ni < 6; ni++)
                    MMA_TF32(acc[mi][ni], a[mi], b[ni]);
        }
        __syncthreads();
    }

    // Epilogue: scatter PRE-CONVERTED tf32 bits to g_q / g_k / g_v
    #pragma unroll
    for (int mi = 0; mi < 2; mi++) {
        const int m1 = m0 + wm * 32 + mi * 16 + g;
        const int b = m1 >> 11, s1 = m1 & 2047;
        #pragma unroll
        for (int ni = 0; ni < 6; ni++) {
            const int colg = wn * 48 + ni * 8 + 2 * tig;
            const int tt = colg >> 6;
            const int d  = colg & 63;
            uint32_t* dst = (tt == 0) ? g_q : (tt == 1) ? g_k : g_v;
            const size_t base = (((size_t)(b * HH + h)) * SS + s1) * DD + d;
            uint2 lo, hi;
            lo.x = cvt_tf32(acc[mi][ni][0]); lo.y = cvt_tf32(acc[mi][ni][1]);
            hi.x = cvt_tf32(acc[mi][ni][2]); hi.y = cvt_tf32(acc[mi][ni][3]);
            *(uint2*)&dst[base] = lo;
            *(uint2*)&dst[base + 8 * DD] = hi;
        }
    }
}

// ===========================================================================
// Kernel 2: flash attention, tf32 mma, 2 CTAs/SM (occupancy hides latency;
// no register prefetch).  CTA = 128 q-rows, k-tiles of 64, 8 warps.
// Dyn smem words: Qs@0 (8704), Ks@8704 (4608), Vs@13312 (4608), Ps@17920
// (8704).  Total 26624 w = 106496 B; x2 CTAs = 213 KB/SM.
// ===========================================================================
#define ATT_SMEM_BYTES (26624 * 4)

__global__ __launch_bounds__(256, 2)
void attn_mma_kernel()
{
    extern __shared__ uint32_t smu[];
    uint32_t* Qs = smu;
    uint32_t* Ks = smu + 8704;
    uint32_t* Vs = smu + 13312;
    uint32_t* Ps = smu + 17920;

    const int qt = (gridDim.x - 1) - blockIdx.x;   // heavy q-tiles first
    const int bh = blockIdx.y;
    const int tid  = threadIdx.x;
    const int wid  = tid >> 5;
    const int lane = tid & 31;
    const int g   = lane >> 2;
    const int tig = lane & 3;
    const int mb  = wid * 16;            // warp's 16 q-rows

    const uint32_t* Qg = g_q + (size_t)bh * SS * DD;
    const uint32_t* Kg = g_k + (size_t)bh * SS * DD;
    const uint32_t* Vg = g_v + (size_t)bh * SS * DD;

    // Load Q tile (pre-converted tf32 bits), stride 68
    {
        const int row = tid >> 1;
        const int dbase = (tid & 1) * 32;
        #pragma unroll
        for (int it = 0; it < 8; it++) {
            const int d0 = dbase + it * 4;
            *(uint4*)&Qs[row * 68 + d0] =
                *(const uint4*)&Qg[(size_t)(qt * 128 + row) * DD + d0];
        }
    }

    float o[8][4];
    #pragma unroll
    for (int ni = 0; ni < 8; ni++)
        #pragma unroll
        for (int j = 0; j < 4; j++) o[ni][j] = 0.f;
    float m0r = -1e30f, m1r = -1e30f, l0 = 0.f, l1 = 0.f;

    const int row0 = qt * 128 + mb + g;       // this thread's even row
    const int njt = 2 * qt + 2;

    const int key = tid >> 2;
    const int db  = (tid & 3) * 16;

    for (int jt = 0; jt < njt; jt++) {
        __syncthreads();   // prior iter done with Ks/Vs (covers Q at jt=0)
        // Load K (transposed) and V directly (co-resident CTA hides latency)
        {
            const size_t kbase = (size_t)(jt * 64 + key) * DD + db;
            #pragma unroll
            for (int it = 0; it < 4; it++) {
                uint4 kv = *(const uint4*)&Kg[kbase + it * 4];
                const int d0 = db + it * 4;
                Ks[(d0+0) * 72 + key] = kv.x;
                Ks[(d0+1) * 72 + key] = kv.y;
                Ks[(d0+2) * 72 + key] = kv.z;
                Ks[(d0+3) * 72 + key] = kv.w;
                *(uint4*)&Vs[key * 72 + d0] = *(const uint4*)&Vg[kbase + it * 4];
            }
        }
        __syncthreads();

        // S = Q @ K^T : 16 rows x 64 keys per warp = 8 n8 tiles, 8 ksteps.
        float sacc[8][4];
        #pragma unroll
        for (int ni = 0; ni < 8; ni++)
            #pragma unroll
            for (int j = 0; j < 4; j++) sacc[ni][j] = 0.f;

        #pragma unroll
        for (int s = 0; s < 8; s++) {
            const int kk = s * 8;
            uint32_t a[4];
            a[0] = Qs[(mb + g    ) * 68 + kk + tig];
            a[1] = Qs[(mb + g + 8) * 68 + kk + tig];
            a[2] = Qs[(mb + g    ) * 68 + kk + tig + 4];
            a[3] = Qs[(mb + g + 8) * 68 + kk + tig + 4];
            #pragma unroll
            for (int ni = 0; ni < 8; ni++) {
                uint32_t b[2];
                b[0] = Ks[(kk + tig    ) * 72 + ni * 8 + g];
                b[1] = Ks[(kk + tig + 4) * 72 + ni * 8 + g];
                MMA_TF32(sacc[ni], a, b);
            }
        }

        // Scale + causal mask
        const bool diag = (jt >= 2 * qt);
        #pragma unroll
        for (int ni = 0; ni < 8; ni++) {
            const int col = jt * 64 + ni * 8 + 2 * tig;
            float v0 = sacc[ni][0] * 0.125f;
            float v1 = sacc[ni][1] * 0.125f;
            float v2 = sacc[ni][2] * 0.125f;
            float v3 = sacc[ni][3] * 0.125f;
            if (diag) {
                if (col     > row0)     v0 = -1e30f;
                if (col + 1 > row0)     v1 = -1e30f;
                if (col     > row0 + 8) v2 = -1e30f;
                if (col + 1 > row0 + 8) v3 = -1e30f;
            }
            sacc[ni][0] = v0; sacc[ni][1] = v1;
            sacc[ni][2] = v2; sacc[ni][3] = v3;
        }

        // Online softmax (rows g and g+8; quad shfl reduce)
        float rmax0 = -1e30f, rmax1 = -1e30f;
        #pragma unroll
        for (int ni = 0; ni < 8; ni++) {
            rmax0 = fmaxf(rmax0, fmaxf(sacc[ni][0], sacc[ni][1]));
            rmax1 = fmaxf(rmax1, fmaxf(sacc[ni][2], sacc[ni][3]));
        }
        rmax0 = fmaxf(rmax0, __shfl_xor_sync(0xffffffffu, rmax0, 1));
        rmax0 = fmaxf(rmax0, __shfl_xor_sync(0xffffffffu, rmax0, 2));
        rmax1 = fmaxf(rmax1, __shfl_xor_sync(0xffffffffu, rmax1, 1));
        rmax1 = fmaxf(rmax1, __shfl_xor_sync(0xffffffffu, rmax1, 2));

        const float mn0 = fmaxf(m0r, rmax0);
        const float mn1 = fmaxf(m1r, rmax1);
        const float corr0 = __expf(m0r - mn0);
        const float corr1 = __expf(m1r - mn1);

        float psum0 = 0.f, psum1 = 0.f;
        #pragma unroll
        for (int ni = 0; ni < 8; ni++) {
            float p0 = __expf(sacc[ni][0] - mn0);
            float p1 = __expf(sacc[ni][1] - mn0);
            float p2 = __expf(sacc[ni][2] - mn1);
            float p3 = __expf(sacc[ni][3] - mn1);
            psum0 += p0 + p1; psum1 += p2 + p3;
            uint2 w0, w1;
            w0.x = cvt_tf32(p0); w0.y = cvt_tf32(p1);
            w1.x = cvt_tf32(p2); w1.y = cvt_tf32(p3);
            *(uint2*)&Ps[(mb + g    ) * 68 + ni * 8 + 2 * tig] = w0;
            *(uint2*)&Ps[(mb + g + 8) * 68 + ni * 8 + 2 * tig] = w1;
        }
        psum0 += __shfl_xor_sync(0xffffffffu, psum0, 1);
        psum0 += __shfl_xor_sync(0xffffffffu, psum0, 2);
        psum1 += __shfl_xor_sync(0xffffffffu, psum1, 1);
        psum1 += __shfl_xor_sync(0xffffffffu, psum1, 2);

        l0 = l0 * corr0 + psum0;  m0r = mn0;
        l1 = l1 * corr1 + psum1;  m1r = mn1;
        #pragma unroll
        for (int ni = 0; ni < 8; ni++) {
            o[ni][0] *= corr0; o[ni][1] *= corr0;
            o[ni][2] *= corr1; o[ni][3] *= corr1;
        }

        __syncwarp();   // Ps visibility within the warp (warp-private buffer)

        // O += P @ V
        #pragma unroll
        for (int s = 0; s < 8; s++) {
            const int kk = s * 8;
            uint32_t a[4];
            a[0] = Ps[(mb + g    ) * 68 + kk + tig];
            a[1] = Ps[(mb + g + 8) * 68 + kk + tig];
            a[2] = Ps[(mb + g    ) * 68 + kk + tig + 4];
            a[3] = Ps[(mb + g + 8) * 68 + kk + tig + 4];
            #pragma unroll
            for (int ni = 0; ni < 8; ni++) {
                uint32_t b[2];
                b[0] = Vs[(kk + tig    ) * 72 + ni * 8 + g];
                b[1] = Vs[(kk + tig + 4) * 72 + ni * 8 + g];
                MMA_TF32(o[ni], a, b);
            }
        }
    }

    // Normalize and store to g_att (fp32)
    float* Og = g_att + (size_t)bh * SS * DD;
    const float inv0 = 1.f / l0;
    const float inv1 = 1.f / l1;
    #pragma unroll
    for (int ni = 0; ni < 8; ni++) {
        const int d = ni * 8 + 2 * tig;
        *(float2*)&Og[(size_t)row0 * DD + d] =
            make_float2(o[ni][0] * inv0, o[ni][1] * inv0);
        *(float2*)&Og[(size_t)(row0 + 8) * DD + d] =
            make_float2(o[ni][2] * inv1, o[ni][3] * inv1);
    }
}

// ===========================================================================
// Kernel 3: output projection, M-tile 64, 2 CTAs/SM.
// Per CTA: 64 M x 128 N, K=512 in BK=32 chunks.  Warp tile 32x32.
// ===========================================================================
__global__ __launch_bounds__(256, 2)
void proj_mma_kernel(const float* __restrict__ Wp,
                     const float* __restrict__ bp,
                     float* __restrict__ out)
{
    __shared__ uint32_t Xs[64 * 36];      //  9216 B
    __shared__ uint32_t Bs[32 * 136];     // 17408 B  (26.6 KB total)

    const int tid  = threadIdx.x;
    const int wid  = tid >> 5;
    const int lane = tid & 31;
    const int n0 = blockIdx.x * 128;
    const int m0 = blockIdx.y * 64;
    const int wm = wid >> 2;
    const int wn = wid & 3;
    const int g   = lane >> 2;
    const int tig = lane & 3;

    const int xrow = tid >> 3;            // 0..31
    const int xc4  = tid & 7;
    size_t abase[2];
    #pragma unroll
    for (int i = 0; i < 2; i++) {
        const int mm = m0 + xrow + 32 * i;
        const int b = mm >> 11, s = mm & 2047;
        abase[i] = ((size_t)b * HH * SS + s) * DD + xc4 * 4;
    }
    const int be  = tid >> 5;
    const int bn4 = tid & 31;
    const uint32_t xsoff = xrow * 36 + xc4 * 4;

    float acc[2][4][4];
    #pragma unroll
    for (int mi = 0; mi < 2; mi++)
        #pragma unroll
        for (int ni = 0; ni < 4; ni++)
            #pragma unroll
            for (int j = 0; j < 4; j++) acc[mi][ni][j] = 0.f;

    // prologue: prefetch chunk 0 (h=0, coff=0)
    float4 xr[2], br[4];
    #pragma unroll
    for (int i = 0; i < 2; i++)
        xr[i] = *(const float4*)&g_att[abase[i]];
    #pragma unroll
    for (int i = 0; i < 4; i++)
        br[i] = *(const float4*)&Wp[(size_t)(be + 8 * i) * EE + n0 + bn4 * 4];

    for (int c = 0; c < 16; c++) {
        #pragma unroll
        for (int i = 0; i < 2; i++)
            *(uint4*)&Xs[xsoff + i * (32 * 36)] = cvt4(xr[i]);
        #pragma unroll
        for (int i = 0; i < 4; i++)
            *(uint4*)&Bs[(be + 8 * i) * 136 + bn4 * 4] = cvt4(br[i]);
        __syncthreads();

        if (c < 15) {
            const int k1 = (c + 1) * 32;
            const int h1 = k1 >> 6;
            const int coff1 = k1 & 63;
            const size_t hoff = (size_t)h1 * SS * DD + coff1;
            #pragma unroll
            for (int i = 0; i < 2; i++)
                xr[i] = *(const float4*)&g_att[abase[i] + hoff];
            #pragma unroll
            for (int i = 0; i < 4; i++)
                br[i] = *(const float4*)&Wp[(size_t)(k1 + be + 8 * i) * EE + n0 + bn4 * 4];
        }

        #pragma unroll
        for (int s = 0; s < 4; s++) {
            const int kk = s * 8;
            uint32_t a[2][4];
            #pragma unroll
            for (int mi = 0; mi < 2; mi++) {
                const int mb = wm * 32 + mi * 16;
                a[mi][0] = Xs[(mb + g    ) * 36 + kk + tig];
                a[mi][1] = Xs[(mb + g + 8) * 36 + kk + tig];
                a[mi][2] = Xs[(mb + g    ) * 36 + kk + tig + 4];
                a[mi][3] = Xs[(mb + g + 8) * 36 + kk + tig + 4];
            }
            uint32_t b[4][2];
            #pragma unroll
            for (int ni = 0; ni < 4; ni++) {
                const int nb = wn * 32 + ni * 8;
                b[ni][0] = Bs[(kk + tig    ) * 136 + nb + g];
                b[ni][1] = Bs[(kk + tig + 4) * 136 + nb + g];
            }
            #pragma unroll
            for (int mi = 0; mi < 2; mi++)
                #pragma unroll
                for (int ni = 0; ni < 4; ni++)
                    MMA_TF32(acc[mi][ni], a[mi], b[ni]);
        }
        __syncthreads();
    }

    #pragma unroll
    for (int mi = 0; mi < 2; mi++) {
        const int m1 = m0 + wm * 32 + mi * 16 + g;
        #pragma unroll
        for (int ni = 0; ni < 4; ni++) {
            const int col = n0 + wn * 32 + ni * 8 + 2 * tig;
            float2 bias = *(const float2*)&bp[col];
            *(float2*)&out[(size_t)m1 * EE + col] =
                make_float2(acc[mi][ni][0] + bias.x, acc[mi][ni][1] + bias.y);
            *(float2*)&out[(size_t)(m1 + 8) * EE + col] =
                make_float2(acc[mi][ni][2] + bias.x, acc[mi][ni][3] + bias.y);
        }
    }
}

// ---------------------------------------------------------------------------
extern "C" void kernel_launch(void* const* d_in, const int* in_sizes, int n_in,
                              void* d_out, int out_size)
{
    const float* x  = (const float*)d_in[0];
    const float* Wq = (const float*)d_in[1];
    const float* Wk = (const float*)d_in[2];
    const float* Wv = (const float*)d_in[3];
    const float* Wp = (const float*)d_in[4];
    const float* bp = (const float*)d_in[5];
    float* out = (float*)d_out;

    (void)in_sizes; (void)n_in; (void)out_size;

    cudaFuncSetAttribute(attn_mma_kernel,
                         cudaFuncAttributeMaxDynamicSharedMemorySize,
                         ATT_SMEM_BYTES);

    // 1) fused QKV projection (M=64 tiles, 2 CTAs/SM)
    qkv_mma_kernel<<<dim3(HH, BS / 64), 256>>>(x, Wq, Wk, Wv);

    // 2) flash attention (2 CTAs/SM, occupancy-hidden loads)
    attn_mma_kernel<<<dim3(SS / 128, BB * HH), 256, ATT_SMEM_BYTES>>>();

    // 3) output projection + bias (M=64 tiles, 2 CTAs/SM)
    proj_mma_kernel<<<dim3(EE / 128, BS / 64), 256>>>(Wp, bp, out);
}

// round 15
// speedup vs baseline: 1.1201x; 1.1201x over previous
#include <cuda_runtime.h>
#include <cstdint>
#include <math.h>

// Problem dims (fixed by the reference)
#define BB 8
#define SS 2048
#define EE 512
#define HH 8
#define DD 64
#define BS (BB*SS)          // 16384 rows

// Scratch: q,k,v hold PRE-CONVERTED tf32 bit patterns; att holds fp32.
__device__ uint32_t g_q[BB*HH*SS*DD];
__device__ uint32_t g_k[BB*HH*SS*DD];
__device__ uint32_t g_v[BB*HH*SS*DD];
__device__ float    g_att[BB*HH*SS*DD];

static __device__ __forceinline__ uint32_t cvt_tf32(float f) {
    uint32_t r; asm("cvt.rna.tf32.f32 %0, %1;" : "=r"(r) : "f"(f)); return r;
}
static __device__ __forceinline__ uint4 cvt4(float4 g) {
    uint4 t;
    t.x = cvt_tf32(g.x); t.y = cvt_tf32(g.y);
    t.z = cvt_tf32(g.z); t.w = cvt_tf32(g.w);
    return t;
}

// m16n8k8 tf32 mma.sync (baseline PTX — no sm_103a-only features)
#define MMA_TF32(c, a, b) \
    asm volatile("mma.sync.aligned.m16n8k8.row.col.f32.tf32.tf32.f32 " \
        "{%0,%1,%2,%3}, {%4,%5,%6,%7}, {%8,%9}, {%0,%1,%2,%3};" \
        : "+f"((c)[0]), "+f"((c)[1]), "+f"((c)[2]), "+f"((c)[3]) \
        : "r"((a)[0]), "r"((a)[1]), "r"((a)[2]), "r"((a)[3]), \
          "r"((b)[0]), "r"((b)[1]))

// ===========================================================================
// Kernel 1: fused QKV projection (R8 structure: reg prefetch, single buffer).
// Per CTA: one head h, 128 M-rows, N=192 (q|k|v), K=512 in BK=32 chunks.
// 8 warps as 2(M)x4(N): warp tile 64x48 = 4 m16 x 6 n8.
// ===========================================================================
__global__ __launch_bounds__(256)
void qkv_mma_kernel(const float* __restrict__ x,
                    const float* __restrict__ Wq,
                    const float* __restrict__ Wk,
                    const float* __restrict__ Wv)
{
    __shared__ uint32_t Xs[128 * 36];     // 18432 B
    __shared__ uint32_t Ws[32 * 200];     // 25600 B

    const int tid  = threadIdx.x;
    const int wid  = tid >> 5;
    const int lane = tid & 31;
    const int h  = blockIdx.x;
    const int m0 = blockIdx.y * 128;
    const int wm = wid >> 2;              // 0..1
    const int wn = wid & 3;               // 0..3
    const int g   = lane >> 2;            // 0..7
    const int tig = lane & 3;             // 0..3

    const int xrow = tid >> 3;
    const int xc4  = tid & 7;
    const float* xptr[4];
    #pragma unroll
    for (int i = 0; i < 4; i++)
        xptr[i] = x + (size_t)(m0 + xrow + 32 * i) * EE + xc4 * 4;

    const int we  = tid >> 4;
    const int wd4 = tid & 15;
    const float* Wsel[3] = { Wq + (size_t)h * EE * DD,
                             Wk + (size_t)h * EE * DD,
                             Wv + (size_t)h * EE * DD };
    const float* wptr[6];
    uint32_t wsoff[6];
    #pragma unroll
    for (int i = 0; i < 6; i++) {
        const int t = i >> 1;
        const int e = we + (i & 1) * 16;
        wptr[i] = Wsel[t] + (size_t)e * DD + wd4 * 4;
        wsoff[i] = e * 200 + t * 64 + wd4 * 4;
    }
    const uint32_t xsoff = xrow * 36 + xc4 * 4;

    float acc[4][6][4];
    #pragma unroll
    for (int mi = 0; mi < 4; mi++)
        #pragma unroll
        for (int ni = 0; ni < 6; ni++)
            #pragma unroll
            for (int j = 0; j < 4; j++) acc[mi][ni][j] = 0.f;

    // prologue: prefetch chunk 0
    float4 xr[4], wr[6];
    #pragma unroll
    for (int i = 0; i < 4; i++) xr[i] = *(const float4*)xptr[i];
    #pragma unroll
    for (int i = 0; i < 6; i++) wr[i] = *(const float4*)wptr[i];

    for (int c = 0; c < 16; c++) {
        // stage current chunk to smem
        #pragma unroll
        for (int i = 0; i < 4; i++)
            *(uint4*)&Xs[xsoff + i * (32 * 36)] = cvt4(xr[i]);
        #pragma unroll
        for (int i = 0; i < 6; i++)
            *(uint4*)&Ws[wsoff[i]] = cvt4(wr[i]);
        __syncthreads();

        // prefetch next chunk (latency hidden behind the MMA block)
        if (c < 15) {
            #pragma unroll
            for (int i = 0; i < 4; i++)
                xr[i] = *(const float4*)(xptr[i] + (c + 1) * 32);
            #pragma unroll
            for (int i = 0; i < 6; i++)
                wr[i] = *(const float4*)(wptr[i] + (size_t)(c + 1) * 32 * DD);
        }

        #pragma unroll
        for (int s = 0; s < 4; s++) {
            const int kk = s * 8;
            uint32_t a[4][4];
            #pragma unroll
            for (int mi = 0; mi < 4; mi++) {
                const int mb = wm * 64 + mi * 16;
                a[mi][0] = Xs[(mb + g    ) * 36 + kk + tig];
                a[mi][1] = Xs[(mb + g + 8) * 36 + kk + tig];
                a[mi][2] = Xs[(mb + g    ) * 36 + kk + tig + 4];
                a[mi][3] = Xs[(mb + g + 8) * 36 + kk + tig + 4];
            }
            uint32_t b[6][2];
            #pragma unroll
            for (int ni = 0; ni < 6; ni++) {
                const int nb = wn * 48 + ni * 8;
                b[ni][0] = Ws[(kk + tig    ) * 200 + nb + g];
                b[ni][1] = Ws[(kk + tig + 4) * 200 + nb + g];
            }
            #pragma unroll
            for (int mi = 0; mi < 4; mi++)
                #pragma unroll
                for (int ni = 0; ni < 6; ni++)
                    MMA_TF32(acc[mi][ni], a[mi], b[ni]);
        }
        __syncthreads();   // MMA done with smem -> safe to overwrite next iter
    }

    // Epilogue: scatter PRE-CONVERTED tf32 bits to g_q / g_k / g_v
    #pragma unroll
    for (int mi = 0; mi < 4; mi++) {
        const int m1 = m0 + wm * 64 + mi * 16 + g;
        const int b = m1 >> 11, s1 = m1 & 2047;
        #pragma unroll
        for (int ni = 0; ni < 6; ni++) {
            const int colg = wn * 48 + ni * 8 + 2 * tig;
            const int tt = colg >> 6;
            const int d  = colg & 63;
            uint32_t* dst = (tt == 0) ? g_q : (tt == 1) ? g_k : g_v;
            const size_t base = (((size_t)(b * HH + h)) * SS + s1) * DD + d;
            uint2 lo, hi;
            lo.x = cvt_tf32(acc[mi][ni][0]); lo.y = cvt_tf32(acc[mi][ni][1]);
            hi.x = cvt_tf32(acc[mi][ni][2]); hi.y = cvt_tf32(acc[mi][ni][3]);
            *(uint2*)&dst[base] = lo;
            *(uint2*)&dst[base + 8 * DD] = hi;
        }
    }
}

// ===========================================================================
// Kernel 2: flash attention (R8 structure + conflict-free K/V staging).
// CTA = 128 q-rows, k-tiles of 64.  8 warps x 16 q-rows each.
// NEW: K stored row-major [key][stride 68] — staging is a direct uint4 copy
// (no transpose), with an XOR column-perm (d^8 when d>=32) making both the
// STS.128 staging and the B-frag LDS conflict-free.  V likewise gets d^4
// when d>=32.  Perms are self-inverse and applied identically at LDS.
// Smem words: Qs@0 (128*68=8704), Ks@8704 (64*68=4352), Vs@13056 (64*72=4608),
// Ps@17664 (128*68=8704).  Total 26368 w = 105472 B.
// ===========================================================================
#define ATT_SMEM_BYTES (26368 * 4)

__global__ __launch_bounds__(256)
void attn_mma_kernel()
{
    extern __shared__ uint32_t smu[];
    uint32_t* Qs = smu;
    uint32_t* Ks = smu + 8704;
    uint32_t* Vs = smu + 13056;
    uint32_t* Ps = smu + 17664;

    const int qt = (gridDim.x - 1) - blockIdx.x;   // heavy q-tiles first
    const int bh = blockIdx.y;
    const int tid  = threadIdx.x;
    const int wid  = tid >> 5;
    const int lane = tid & 31;
    const int g   = lane >> 2;
    const int tig = lane & 3;
    const int mb  = wid * 16;            // warp's 16 q-rows

    const uint32_t* Qg = g_q + (size_t)bh * SS * DD;
    const uint32_t* Kg = g_k + (size_t)bh * SS * DD;
    const uint32_t* Vg = g_v + (size_t)bh * SS * DD;

    // Load Q tile (pre-converted tf32 bits), stride 68
    {
        const int row = tid >> 1;
        const int dbase = (tid & 1) * 32;
        #pragma unroll
        for (int it = 0; it < 8; it++) {
            const int d0 = dbase + it * 4;
            *(uint4*)&Qs[row * 68 + d0] =
                *(const uint4*)&Qg[(size_t)(qt * 128 + row) * DD + d0];
        }
    }

    float o[8][4];
    #pragma unroll
    for (int ni = 0; ni < 8; ni++)
        #pragma unroll
        for (int j = 0; j < 4; j++) o[ni][j] = 0.f;
    float m0r = -1e30f, m1r = -1e30f, l0 = 0.f, l1 = 0.f;

    const int row0 = qt * 128 + mb + g;       // this thread's even row
    const int njt = 2 * qt + 2;

    // K/V load coords: thread owns key = tid>>2, d-block db = (tid&3)*16
    const int key = tid >> 2;
    const int db  = (tid & 3) * 16;

    // prologue: prefetch k-tile 0
    uint4 kr[4], vr[4];
    #pragma unroll
    for (int it = 0; it < 4; it++) {
        kr[it] = *(const uint4*)&Kg[(size_t)key * DD + db + it * 4];
        vr[it] = *(const uint4*)&Vg[(size_t)key * DD + db + it * 4];
    }

    for (int jt = 0; jt < njt; jt++) {
        __syncthreads();   // prior iter done with Ks/Vs (covers Q at jt=0)
        // stage K and V from prefetch regs: direct uint4 copies, XOR-perm'd.
        #pragma unroll
        for (int it = 0; it < 4; it++) {
            const int d0 = db + it * 4;
            const int kd = d0 ^ ((d0 & 32) ? 8 : 0);
            const int vd = d0 ^ ((d0 & 32) ? 4 : 0);
            *(uint4*)&Ks[key * 68 + kd] = kr[it];
            *(uint4*)&Vs[key * 72 + vd] = vr[it];
        }
        __syncthreads();

        // prefetch next tile (hidden behind S-MMA + softmax + PV-MMA)
        if (jt + 1 < njt) {
            const size_t kbase = (size_t)((jt + 1) * 64 + key) * DD + db;
            #pragma unroll
            for (int it = 0; it < 4; it++) {
                kr[it] = *(const uint4*)&Kg[kbase + it * 4];
                vr[it] = *(const uint4*)&Vg[kbase + it * 4];
            }
        }

        // S = Q @ K^T : 16 rows x 64 keys per warp = 8 n8 tiles, 8 ksteps.
        float sacc[8][4];
        #pragma unroll
        for (int ni = 0; ni < 8; ni++)
            #pragma unroll
            for (int j = 0; j < 4; j++) sacc[ni][j] = 0.f;

        #pragma unroll
        for (int s = 0; s < 8; s++) {
            const int kk = s * 8;
            const int kperm = (kk & 32) ? 8 : 0;   // (kk+tig[+4]) >> 5 == kk>>5
            uint32_t a[4];
            a[0] = Qs[(mb + g    ) * 68 + kk + tig];
            a[1] = Qs[(mb + g + 8) * 68 + kk + tig];
            a[2] = Qs[(mb + g    ) * 68 + kk + tig + 4];
            a[3] = Qs[(mb + g + 8) * 68 + kk + tig + 4];
            #pragma unroll
            for (int ni = 0; ni < 8; ni++) {
                const int nb = ni * 8 + g;
                uint32_t b[2];
                b[0] = Ks[nb * 68 + ((kk + tig    ) ^ kperm)];
                b[1] = Ks[nb * 68 + ((kk + tig + 4) ^ kperm)];
                MMA_TF32(sacc[ni], a, b);
            }
        }

        // Scale + causal mask
        const bool diag = (jt >= 2 * qt);
        #pragma unroll
        for (int ni = 0; ni < 8; ni++) {
            const int col = jt * 64 + ni * 8 + 2 * tig;
            float v0 = sacc[ni][0] * 0.125f;
            float v1 = sacc[ni][1] * 0.125f;
            float v2 = sacc[ni][2] * 0.125f;
            float v3 = sacc[ni][3] * 0.125f;
            if (diag) {
                if (col     > row0)     v0 = -1e30f;
                if (col + 1 > row0)     v1 = -1e30f;
                if (col     > row0 + 8) v2 = -1e30f;
                if (col + 1 > row0 + 8) v3 = -1e30f;
            }
            sacc[ni][0] = v0; sacc[ni][1] = v1;
            sacc[ni][2] = v2; sacc[ni][3] = v3;
        }

        // Online softmax (rows g and g+8; quad shfl reduce)
        float rmax0 = -1e30f, rmax1 = -1e30f;
        #pragma unroll
        for (int ni = 0; ni < 8; ni++) {
            rmax0 = fmaxf(rmax0, fmaxf(sacc[ni][0], sacc[ni][1]));
            rmax1 = fmaxf(rmax1, fmaxf(sacc[ni][2], sacc[ni][3]));
        }
        rmax0 = fmaxf(rmax0, __shfl_xor_sync(0xffffffffu, rmax0, 1));
        rmax0 = fmaxf(rmax0, __shfl_xor_sync(0xffffffffu, rmax0, 2));
        rmax1 = fmaxf(rmax1, __shfl_xor_sync(0xffffffffu, rmax1, 1));
        rmax1 = fmaxf(rmax1, __shfl_xor_sync(0xffffffffu, rmax1, 2));

        const float mn0 = fmaxf(m0r, rmax0);
        const float mn1 = fmaxf(m1r, rmax1);
        const float corr0 = __expf(m0r - mn0);
        const float corr1 = __expf(m1r - mn1);

        float psum0 = 0.f, psum1 = 0.f;
        #pragma unroll
        for (int ni = 0; ni < 8; ni++) {
            float p0 = __expf(sacc[ni][0] - mn0);
            float p1 = __expf(sacc[ni][1] - mn0);
            float p2 = __expf(sacc[ni][2] - mn1);
            float p3 = __expf(sacc[ni][3] - mn1);
            psum0 += p0 + p1; psum1 += p2 + p3;
            uint2 w0, w1;
            w0.x = cvt_tf32(p0); w0.y = cvt_tf32(p1);
            w1.x = cvt_tf32(p2); w1.y = cvt_tf32(p3);
            *(uint2*)&Ps[(mb + g    ) * 68 + ni * 8 + 2 * tig] = w0;
            *(uint2*)&Ps[(mb + g + 8) * 68 + ni * 8 + 2 * tig] = w1;
        }
        psum0 += __shfl_xor_sync(0xffffffffu, psum0, 1);
        psum0 += __shfl_xor_sync(0xffffffffu, psum0, 2);
        psum1 += __shfl_xor_sync(0xffffffffu, psum1, 1);
        psum1 += __shfl_xor_sync(0xffffffffu, psum1, 2);

        l0 = l0 * corr0 + psum0;  m0r = mn0;
        l1 = l1 * corr1 + psum1;  m1r = mn1;
        #pragma unroll
        for (int ni = 0; ni < 8; ni++) {
            o[ni][0] *= corr0; o[ni][1] *= corr0;
            o[ni][2] *= corr1; o[ni][3] *= corr1;
        }

        __syncwarp();   // Ps visibility within the warp (warp-private buffer)

        // O += P @ V  (V column-perm: col^4 when col>=32, i.e. ni>=4)
        #pragma unroll
        for (int s = 0; s < 8; s++) {
            const int kk = s * 8;
            uint32_t a[4];
            a[0] = Ps[(mb + g    ) * 68 + kk + tig];
            a[1] = Ps[(mb + g + 8) * 68 + kk + tig];
            a[2] = Ps[(mb + g    ) * 68 + kk + tig + 4];
            a[3] = Ps[(mb + g + 8) * 68 + kk + tig + 4];
            #pragma unroll
            for (int ni = 0; ni < 8; ni++) {
                const int colp = (ni * 8 + g) ^ ((ni & 4) ? 4 : 0);
                uint32_t b[2];
                b[0] = Vs[(kk + tig    ) * 72 + colp];
                b[1] = Vs[(kk + tig + 4) * 72 + colp];
                MMA_TF32(o[ni], a, b);
            }
        }
    }

    // Normalize and store to g_att (fp32)
    float* Og = g_att + (size_t)bh * SS * DD;
    const float inv0 = 1.f / l0;
    const float inv1 = 1.f / l1;
    #pragma unroll
    for (int ni = 0; ni < 8; ni++) {
        const int d = ni * 8 + 2 * tig;
        *(float2*)&Og[(size_t)row0 * DD + d] =
            make_float2(o[ni][0] * inv0, o[ni][1] * inv0);
        *(float2*)&Og[(size_t)(row0 + 8) * DD + d] =
            make_float2(o[ni][2] * inv1, o[ni][3] * inv1);
    }
}

// ===========================================================================
// Kernel 3: output projection (R8 structure: reg prefetch, single buffer).
// Per CTA: 128 M x 128 N, K=512 in BK=32 chunks.
// ===========================================================================
__global__ __launch_bounds__(256)
void proj_mma_kernel(const float* __restrict__ Wp,
                     const float* __restrict__ bp,
                     float* __restrict__ out)
{
    __shared__ uint32_t Xs[128 * 36];
    __shared__ uint32_t Bs[32 * 136];

    const int tid  = threadIdx.x;
    const int wid  = tid >> 5;
    const int lane = tid & 31;
    const int n0 = blockIdx.x * 128;
    const int m0 = blockIdx.y * 128;
    const int wm = wid >> 2;
    const int wn = wid & 3;
    const int g   = lane >> 2;
    const int tig = lane & 3;

    const int xrow = tid >> 3;
    const int xc4  = tid & 7;
    size_t abase[4];
    #pragma unroll
    for (int i = 0; i < 4; i++) {
        const int mm = m0 + xrow + 32 * i;
        const int b = mm >> 11, s = mm & 2047;
        abase[i] = ((size_t)b * HH * SS + s) * DD + xc4 * 4;
    }
    const int be  = tid >> 5;
    const int bn4 = tid & 31;
    const uint32_t xsoff = xrow * 36 + xc4 * 4;

    float acc[4][4][4];
    #pragma unroll
    for (int mi = 0; mi < 4; mi++)
        #pragma unroll
        for (int ni = 0; ni < 4; ni++)
            #pragma unroll
            for (int j = 0; j < 4; j++) acc[mi][ni][j] = 0.f;

    // prologue: prefetch chunk 0 (h=0, coff=0)
    float4 xr[4], br[4];
    #pragma unroll
    for (int i = 0; i < 4; i++)
        xr[i] = *(const float4*)&g_att[abase[i]];
    #pragma unroll
    for (int i = 0; i < 4; i++)
        br[i] = *(const float4*)&Wp[(size_t)(be + 8 * i) * EE + n0 + bn4 * 4];

    for (int c = 0; c < 16; c++) {
        #pragma unroll
        for (int i = 0; i < 4; i++)
            *(uint4*)&Xs[xsoff + i * (32 * 36)] = cvt4(xr[i]);
        #pragma unroll
        for (int i = 0; i < 4; i++)
            *(uint4*)&Bs[(be + 8 * i) * 136 + bn4 * 4] = cvt4(br[i]);
        __syncthreads();

        if (c < 15) {
            const int k1 = (c + 1) * 32;
            const int h1 = k1 >> 6;
            const int coff1 = k1 & 63;
            const size_t hoff = (size_t)h1 * SS * DD + coff1;
            #pragma unroll
            for (int i = 0; i < 4; i++)
                xr[i] = *(const float4*)&g_att[abase[i] + hoff];
            #pragma unroll
            for (int i = 0; i < 4; i++)
                br[i] = *(const float4*)&Wp[(size_t)(k1 + be + 8 * i) * EE + n0 + bn4 * 4];
        }

        #pragma unroll
        for (int s = 0; s < 4; s++) {
            const int kk = s * 8;
            uint32_t a[4][4];
            #pragma unroll
            for (int mi = 0; mi < 4; mi++) {
                const int mb = wm * 64 + mi * 16;
                a[mi][0] = Xs[(mb + g    ) * 36 + kk + tig];
                a[mi][1] = Xs[(mb + g + 8) * 36 + kk + tig];
                a[mi][2] = Xs[(mb + g    ) * 36 + kk + tig + 4];
                a[mi][3] = Xs[(mb + g + 8) * 36 + kk + tig + 4];
            }
            uint32_t b[4][2];
            #pragma unroll
            for (int ni = 0; ni < 4; ni++) {
                const int nb = wn * 32 + ni * 8;
                b[ni][0] = Bs[(kk + tig    ) * 136 + nb + g];
                b[ni][1] = Bs[(kk + tig + 4) * 136 + nb + g];
            }
            #pragma unroll
            for (int mi = 0; mi < 4; mi++)
                #pragma unroll
                for (int ni = 0; ni < 4; ni++)
                    MMA_TF32(acc[mi][ni], a[mi], b[ni]);
        }
        __syncthreads();
    }

    #pragma unroll
    for (int mi = 0; mi < 4; mi++) {
        const int m1 = m0 + wm * 64 + mi * 16 + g;
        #pragma unroll
        for (int ni = 0; ni < 4; ni++) {
            const int col = n0 + wn * 32 + ni * 8 + 2 * tig;
            float2 bias = *(const float2*)&bp[col];
            *(float2*)&out[(size_t)m1 * EE + col] =
                make_float2(acc[mi][ni][0] + bias.x, acc[mi][ni][1] + bias.y);
            *(float2*)&out[(size_t)(m1 + 8) * EE + col] =
                make_float2(acc[mi][ni][2] + bias.x, acc[mi][ni][3] + bias.y);
        }
    }
}

// ---------------------------------------------------------------------------
extern "C" void kernel_launch(void* const* d_in, const int* in_sizes, int n_in,
                              void* d_out, int out_size)
{
    const float* x  = (const float*)d_in[0];
    const float* Wq = (const float*)d_in[1];
    const float* Wk = (const float*)d_in[2];
    const float* Wv = (const float*)d_in[3];
    const float* Wp = (const float*)d_in[4];
    const float* bp = (const float*)d_in[5];
    float* out = (float*)d_out;

    (void)in_sizes; (void)n_in; (void)out_size;

    cudaFuncSetAttribute(attn_mma_kernel,
                         cudaFuncAttributeMaxDynamicSharedMemorySize,
                         ATT_SMEM_BYTES);

    // 1) fused QKV projection (mma.sync tf32, reg-prefetch pipeline)
    qkv_mma_kernel<<<dim3(HH, BS / 128), 256>>>(x, Wq, Wk, Wv);

    // 2) flash attention (conflict-free K/V staging, reg prefetch)
    attn_mma_kernel<<<dim3(SS / 128, BB * HH), 256, ATT_SMEM_BYTES>>>();

    // 3) output projection + bias (mma.sync tf32, reg-prefetch pipeline)
    proj_mma_kernel<<<dim3(EE / 128, BS / 128), 256>>>(Wp, bp, out);
}